// round 9
// baseline (speedup 1.0000x reference)
#include <cuda_runtime.h>
#include <cstdint>

#define BB 4
#define CC 192
#define NN 4096
#define KK 9
#define TK 8

__device__ __align__(256) float g_xn[(size_t)BB * CC * NN];   // normalized pts [b][c][n]
__device__ __align__(256) float g_sq[(size_t)BB * NN];        // per-point sum of squares
__device__ __align__(256) float g_dist[(size_t)BB * NN * NN]; // distance matrix

// ---------------------------------------------------------------------------
// Kernel 1: L2-normalize over channel dim. x layout [B][C][N], N = H*W.
// ---------------------------------------------------------------------------
__global__ void normalize_kernel(const float* __restrict__ x) {
    int b = blockIdx.y;
    int n = blockIdx.x * blockDim.x + threadIdx.x;
    if (n >= NN) return;
    const float* xb = x + (size_t)b * CC * NN + n;
    float s = 0.f;
    #pragma unroll 16
    for (int c = 0; c < CC; c++) { float v = xb[(size_t)c * NN]; s += v * v; }
    float denom = fmaxf(sqrtf(s), 1e-12f);
    float* xnb = g_xn + (size_t)b * CC * NN + n;
    float sq = 0.f;
    #pragma unroll 16
    for (int c = 0; c < CC; c++) {
        float p = xb[(size_t)c * NN] / denom;
        xnb[(size_t)c * NN] = p;
        sq += p * p;
    }
    g_sq[(size_t)b * NN + n] = sq;
}

// ---------------------------------------------------------------------------
// Kernel 2: dist[b][n][m] = (sq[n] + (-2*dot(n,m))) + sq[m]
// 128x128 tile, TK=8, double-buffered smem, reg-prefetch, 8x8 per thread.
// Per-dot k-accumulation order identical to round-8 kernel (c ascending).
// ---------------------------------------------------------------------------
__global__ __launch_bounds__(256, 2) void dist_gemm_kernel() {
    __shared__ float As[2][TK][128];
    __shared__ float Bs[2][TK][128];

    const int b  = blockIdx.z;
    const int n0 = blockIdx.y * 128;
    const int m0 = blockIdx.x * 128;
    const float* base = g_xn + (size_t)b * CC * NN;
    const int tid = threadIdx.x;
    const int tx = tid & 15;        // m micro-tile
    const int ty = tid >> 4;        // n micro-tile

    // loader mapping: 8 rows x 32 float4-cols per tile, 256 threads -> 1 slot
    const int lr = tid >> 5;        // 0..7  (k row within tile)
    const int lc = (tid & 31) * 4;  // 0..124 (float col, x4)

    float4 pa, pb;
    {
        const float* src = base + (size_t)lr * NN;
        pa = *(const float4*)(src + n0 + lc);
        pb = *(const float4*)(src + m0 + lc);
    }
    *(float4*)&As[0][lr][lc] = pa;
    *(float4*)&Bs[0][lr][lc] = pb;
    __syncthreads();

    float acc[8][8];
    #pragma unroll
    for (int i = 0; i < 8; i++)
        #pragma unroll
        for (int j = 0; j < 8; j++) acc[i][j] = 0.f;

    const int NT = CC / TK;   // 24
    #pragma unroll 1
    for (int t = 0; t < NT; t++) {
        const int cur = t & 1;

        if (t + 1 < NT) {   // prefetch next tile into registers
            const float* src = base + (size_t)((t + 1) * TK + lr) * NN;
            pa = *(const float4*)(src + n0 + lc);
            pb = *(const float4*)(src + m0 + lc);
        }

        #pragma unroll
        for (int kk = 0; kk < TK; kk++) {
            float a[8], bv[8];
            *(float4*)&a[0]  = *(float4*)&As[cur][kk][ty * 8];
            *(float4*)&a[4]  = *(float4*)&As[cur][kk][ty * 8 + 4];
            *(float4*)&bv[0] = *(float4*)&Bs[cur][kk][tx * 8];
            *(float4*)&bv[4] = *(float4*)&Bs[cur][kk][tx * 8 + 4];
            #pragma unroll
            for (int i = 0; i < 8; i++)
                #pragma unroll
                for (int j = 0; j < 8; j++)
                    acc[i][j] += a[i] * bv[j];
        }

        if (t + 1 < NT) {   // store prefetched tile into the other buffer
            *(float4*)&As[cur ^ 1][lr][lc] = pa;
            *(float4*)&Bs[cur ^ 1][lr][lc] = pb;
        }
        __syncthreads();
    }

    const float* sqb = g_sq + (size_t)b * NN;
    float sqm[8];
    #pragma unroll
    for (int j = 0; j < 8; j++) sqm[j] = sqb[m0 + tx * 8 + j];
    #pragma unroll
    for (int i = 0; i < 8; i++) {
        int n = n0 + ty * 8 + i;
        float sqn = sqb[n];
        float* drow = g_dist + ((size_t)b * NN + n) * NN + m0 + tx * 8;
        float d[8];
        #pragma unroll
        for (int j = 0; j < 8; j++)
            d[j] = (sqn + (-2.0f * acc[i][j])) + sqm[j];
        *(float4*)&drow[0] = make_float4(d[0], d[1], d[2], d[3]);
        *(float4*)&drow[4] = make_float4(d[4], d[5], d[6], d[7]);
    }
}

// ---------------------------------------------------------------------------
// Kernel 3: warp-per-row top-10 ascending (dist, idx); drop rank 0 (self).
// float4 reads; selection uses a total order so scan order is irrelevant.
// ---------------------------------------------------------------------------
__device__ __forceinline__ unsigned ford(float f) {
    unsigned u = __float_as_uint(f);
    return (u & 0x80000000u) ? ~u : (u | 0x80000000u);
}

__global__ void select_topk_kernel(float* __restrict__ out) {
    const int warp = (blockIdx.x * blockDim.x + threadIdx.x) >> 5;
    const int lane = threadIdx.x & 31;
    if (warp >= BB * NN) return;
    const int row = warp;
    const int b = row >> 12;
    const int n = row & (NN - 1);
    const float4* drow4 = (const float4*)(g_dist + (size_t)row * NN);

    float v[10]; int id[10];
    #pragma unroll
    for (int k = 0; k < 10; k++) { v[k] = 3.4e38f; id[k] = 0x7FFFFFFF; }

    #pragma unroll 1
    for (int i = 0; i < NN / 128; i++) {
        float4 dv = drow4[lane + i * 32];
        int m0 = (lane + i * 32) * 4;
        float dd[4] = {dv.x, dv.y, dv.z, dv.w};
        #pragma unroll
        for (int q = 0; q < 4; q++) {
            float val = dd[q];
            int m = m0 + q;
            if ((val < v[9]) || (val == v[9] && m < id[9])) {
                v[9] = val; id[9] = m;
                #pragma unroll
                for (int k = 9; k > 0; k--) {
                    bool sw = (v[k] < v[k-1]) || (v[k] == v[k-1] && id[k] < id[k-1]);
                    if (sw) {
                        float tv = v[k]; v[k] = v[k-1]; v[k-1] = tv;
                        int ti = id[k]; id[k] = id[k-1]; id[k-1] = ti;
                    }
                }
            }
        }
    }

    const size_t L = (size_t)BB * NN * KK;
    const size_t outbase = (size_t)row * KK;
    int pos = 0;
    for (int k = 0; k < 10; k++) {
        unsigned long long myk = (pos < 10)
            ? (((unsigned long long)ford(v[pos]) << 32) | (unsigned)id[pos])
            : 0xFFFFFFFFFFFFFFFFULL;
        unsigned long long mn = myk;
        #pragma unroll
        for (int off = 16; off > 0; off >>= 1) {
            unsigned long long o = __shfl_xor_sync(0xFFFFFFFFu, mn, off);
            mn = (o < mn) ? o : mn;
        }
        if (myk == mn) pos++;
        if (k > 0 && lane == 0)
            out[outbase + (k - 1)] = (float)((int)(mn & 0xFFFFFFFFu) + b * NN);
    }
    if (lane < KK) out[L + outbase + lane] = (float)(n + b * NN);
}

// ---------------------------------------------------------------------------
extern "C" void kernel_launch(void* const* d_in, const int* in_sizes, int n_in,
                              void* d_out, int out_size) {
    const float* x = (const float*)d_in[0];
    float* out = (float*)d_out;

    { dim3 grid(NN / 256, BB); normalize_kernel<<<grid, 256>>>(x); }
    { dim3 grid(NN / 128, NN / 128, BB); dist_gemm_kernel<<<grid, 256>>>(); }
    { int rows = BB * NN; select_topk_kernel<<<(rows * 32 + 255) / 256, 256>>>(out); }
}

// round 10
// speedup vs baseline: 1.0028x; 1.0028x over previous
#include <cuda_runtime.h>
#include <cstdint>

#define BB 4
#define CC 192
#define NN 4096
#define KK 9
#define TK 16

__device__ __align__(256) float g_xn[(size_t)BB * CC * NN];   // normalized pts [b][c][n]
__device__ __align__(256) float g_sq[(size_t)BB * NN];        // per-point sum of squares
__device__ __align__(256) float g_dist[(size_t)BB * NN * NN]; // distance matrix

__device__ __forceinline__ void cp_async16(void* smem_dst, const void* gmem_src) {
    unsigned saddr = (unsigned)__cvta_generic_to_shared(smem_dst);
    asm volatile("cp.async.ca.shared.global [%0], [%1], 16;\n" :: "r"(saddr), "l"(gmem_src));
}
__device__ __forceinline__ void cp_commit() {
    asm volatile("cp.async.commit_group;\n");
}
template <int N>
__device__ __forceinline__ void cp_wait() {
    asm volatile("cp.async.wait_group %0;\n" :: "n"(N));
}

// ---------------------------------------------------------------------------
// Kernel 1: L2-normalize over channel dim. x layout [B][C][N], N = H*W.
// ---------------------------------------------------------------------------
__global__ void normalize_kernel(const float* __restrict__ x) {
    int b = blockIdx.y;
    int n = blockIdx.x * blockDim.x + threadIdx.x;
    if (n >= NN) return;
    const float* xb = x + (size_t)b * CC * NN + n;
    float s = 0.f;
    #pragma unroll 16
    for (int c = 0; c < CC; c++) { float v = xb[(size_t)c * NN]; s += v * v; }
    float denom = fmaxf(sqrtf(s), 1e-12f);
    float* xnb = g_xn + (size_t)b * CC * NN + n;
    float sq = 0.f;
    #pragma unroll 16
    for (int c = 0; c < CC; c++) {
        float p = xb[(size_t)c * NN] / denom;
        xnb[(size_t)c * NN] = p;
        sq += p * p;
    }
    g_sq[(size_t)b * NN + n] = sq;
}

// ---------------------------------------------------------------------------
// Kernel 2: dist[b][n][m] = (sq[n] + (-2*dot(n,m))) + sq[m]
// 128x128 tile, TK=16, cp.async double-buffered smem, 8x8 per thread.
// Per-dot k order: c ascending (identical to rounds 8/9 -> same rel_err).
// ---------------------------------------------------------------------------
__global__ __launch_bounds__(256) void dist_gemm_kernel() {
    __shared__ float As[2][TK][128];
    __shared__ float Bs[2][TK][128];

    const int b  = blockIdx.z;
    const int n0 = blockIdx.y * 128;
    const int m0 = blockIdx.x * 128;
    const float* base = g_xn + (size_t)b * CC * NN;
    const int tid = threadIdx.x;
    const int tx = tid & 15;        // m micro-tile
    const int ty = tid >> 4;        // n micro-tile

    // loader: each thread moves rows lr and lr+8, one float4 column slot
    const int lr = tid >> 5;        // 0..7
    const int lc = (tid & 31) * 4;  // 0..124

    const int NT = CC / TK;         // 12

    // preload tile 0
    {
        const float* s0 = base + (size_t)lr * NN;
        const float* s1 = base + (size_t)(lr + 8) * NN;
        cp_async16(&As[0][lr][lc],     s0 + n0 + lc);
        cp_async16(&As[0][lr + 8][lc], s1 + n0 + lc);
        cp_async16(&Bs[0][lr][lc],     s0 + m0 + lc);
        cp_async16(&Bs[0][lr + 8][lc], s1 + m0 + lc);
        cp_commit();
    }

    float acc[8][8];
    #pragma unroll
    for (int i = 0; i < 8; i++)
        #pragma unroll
        for (int j = 0; j < 8; j++) acc[i][j] = 0.f;

    #pragma unroll 1
    for (int t = 0; t < NT; t++) {
        const int cur = t & 1;

        if (t + 1 < NT) {
            const int c1 = (t + 1) * TK;
            const float* s0 = base + (size_t)(c1 + lr) * NN;
            const float* s1 = base + (size_t)(c1 + lr + 8) * NN;
            cp_async16(&As[cur ^ 1][lr][lc],     s0 + n0 + lc);
            cp_async16(&As[cur ^ 1][lr + 8][lc], s1 + n0 + lc);
            cp_async16(&Bs[cur ^ 1][lr][lc],     s0 + m0 + lc);
            cp_async16(&Bs[cur ^ 1][lr + 8][lc], s1 + m0 + lc);
            cp_commit();
            cp_wait<1>();   // current tile's group complete; prefetch in flight
        } else {
            cp_wait<0>();
        }
        __syncthreads();

        #pragma unroll
        for (int kk = 0; kk < TK; kk++) {
            float a[8], bv[8];
            *(float4*)&a[0]  = *(float4*)&As[cur][kk][ty * 8];
            *(float4*)&a[4]  = *(float4*)&As[cur][kk][ty * 8 + 4];
            *(float4*)&bv[0] = *(float4*)&Bs[cur][kk][tx * 8];
            *(float4*)&bv[4] = *(float4*)&Bs[cur][kk][tx * 8 + 4];
            #pragma unroll
            for (int i = 0; i < 8; i++)
                #pragma unroll
                for (int j = 0; j < 8; j++)
                    acc[i][j] += a[i] * bv[j];
        }
        __syncthreads();   // done reading cur before next prefetch overwrites it
    }

    const float* sqb = g_sq + (size_t)b * NN;
    float sqm[8];
    #pragma unroll
    for (int j = 0; j < 8; j++) sqm[j] = sqb[m0 + tx * 8 + j];
    #pragma unroll
    for (int i = 0; i < 8; i++) {
        int n = n0 + ty * 8 + i;
        float sqn = sqb[n];
        float* drow = g_dist + ((size_t)b * NN + n) * NN + m0 + tx * 8;
        float d[8];
        #pragma unroll
        for (int j = 0; j < 8; j++)
            d[j] = (sqn + (-2.0f * acc[i][j])) + sqm[j];
        *(float4*)&drow[0] = make_float4(d[0], d[1], d[2], d[3]);
        *(float4*)&drow[4] = make_float4(d[4], d[5], d[6], d[7]);
    }
}

// ---------------------------------------------------------------------------
// Kernel 3: warp-per-row top-10 ascending (dist, idx); drop rank 0 (self).
// ---------------------------------------------------------------------------
__device__ __forceinline__ unsigned ford(float f) {
    unsigned u = __float_as_uint(f);
    return (u & 0x80000000u) ? ~u : (u | 0x80000000u);
}

__global__ void select_topk_kernel(float* __restrict__ out) {
    const int warp = (blockIdx.x * blockDim.x + threadIdx.x) >> 5;
    const int lane = threadIdx.x & 31;
    if (warp >= BB * NN) return;
    const int row = warp;
    const int b = row >> 12;
    const int n = row & (NN - 1);
    const float4* drow4 = (const float4*)(g_dist + (size_t)row * NN);

    float v[10]; int id[10];
    #pragma unroll
    for (int k = 0; k < 10; k++) { v[k] = 3.4e38f; id[k] = 0x7FFFFFFF; }

    #pragma unroll 1
    for (int i = 0; i < NN / 128; i++) {
        float4 dv = drow4[lane + i * 32];
        int mb = (lane + i * 32) * 4;
        float dd[4] = {dv.x, dv.y, dv.z, dv.w};
        #pragma unroll
        for (int q = 0; q < 4; q++) {
            float val = dd[q];
            int m = mb + q;
            if ((val < v[9]) || (val == v[9] && m < id[9])) {
                v[9] = val; id[9] = m;
                #pragma unroll
                for (int k = 9; k > 0; k--) {
                    bool sw = (v[k] < v[k-1]) || (v[k] == v[k-1] && id[k] < id[k-1]);
                    if (sw) {
                        float tv = v[k]; v[k] = v[k-1]; v[k-1] = tv;
                        int ti = id[k]; id[k] = id[k-1]; id[k-1] = ti;
                    }
                }
            }
        }
    }

    const size_t L = (size_t)BB * NN * KK;
    const size_t outbase = (size_t)row * KK;
    int pos = 0;
    for (int k = 0; k < 10; k++) {
        unsigned long long myk = (pos < 10)
            ? (((unsigned long long)ford(v[pos]) << 32) | (unsigned)id[pos])
            : 0xFFFFFFFFFFFFFFFFULL;
        unsigned long long mn = myk;
        #pragma unroll
        for (int off = 16; off > 0; off >>= 1) {
            unsigned long long o = __shfl_xor_sync(0xFFFFFFFFu, mn, off);
            mn = (o < mn) ? o : mn;
        }
        if (myk == mn) pos++;
        if (k > 0 && lane == 0)
            out[outbase + (k - 1)] = (float)((int)(mn & 0xFFFFFFFFu) + b * NN);
    }
    if (lane < KK) out[L + outbase + lane] = (float)(n + b * NN);
}

// ---------------------------------------------------------------------------
extern "C" void kernel_launch(void* const* d_in, const int* in_sizes, int n_in,
                              void* d_out, int out_size) {
    const float* x = (const float*)d_in[0];
    float* out = (float*)d_out;

    { dim3 grid(NN / 256, BB); normalize_kernel<<<grid, 256>>>(x); }
    { dim3 grid(NN / 128, NN / 128, BB); dist_gemm_kernel<<<grid, 256>>>(); }
    { int rows = BB * NN; select_topk_kernel<<<(rows * 32 + 255) / 256, 256>>>(out); }
}

// round 11
// speedup vs baseline: 1.4526x; 1.4485x over previous
#include <cuda_runtime.h>
#include <cstdint>

#define BB 4
#define CC 192
#define NN 4096
#define KK 9

__device__ __align__(256) float g_xn[(size_t)BB * CC * NN];   // normalized pts [b][c][n]
__device__ __align__(256) float g_sq[(size_t)BB * NN];        // per-point sum of squares
__device__ __align__(256) float g_dist[(size_t)BB * NN * NN]; // distance matrix

// ---------------------------------------------------------------------------
// Kernel 1: L2-normalize over channel dim. x layout [B][C][N], N = H*W.
// ---------------------------------------------------------------------------
__global__ void normalize_kernel(const float* __restrict__ x) {
    int b = blockIdx.y;
    int n = blockIdx.x * blockDim.x + threadIdx.x;
    if (n >= NN) return;
    const float* xb = x + (size_t)b * CC * NN + n;
    float s = 0.f;
    #pragma unroll 16
    for (int c = 0; c < CC; c++) { float v = xb[(size_t)c * NN]; s += v * v; }
    float denom = fmaxf(sqrtf(s), 1e-12f);
    float* xnb = g_xn + (size_t)b * CC * NN + n;
    float sq = 0.f;
    #pragma unroll 16
    for (int c = 0; c < CC; c++) {
        float p = xb[(size_t)c * NN] / denom;
        xnb[(size_t)c * NN] = p;
        sq += p * p;
    }
    g_sq[(size_t)b * NN + n] = sq;
}

// ---------------------------------------------------------------------------
// Kernel 2: symmetric distance GEMM. Only upper-triangular 128x128 tile pairs
// (bi <= bj) are computed; off-diagonal tiles also emit the mirrored tile via
// an smem-staged transpose. Inner loop is the round-8 (known-good) version.
//   normal:   dist[n][m] = (sq[n] + (-2*acc)) + sq[m]
//   mirrored: dist[m][n] = (sq[m] + (-2*acc)) + sq[n]
// ---------------------------------------------------------------------------
__global__ __launch_bounds__(256) void dist_gemm_sym_kernel() {
    __shared__ union {
        float ab[2][16][128];     // As/Bs during k-loop
        float ts[128 * 65];       // transpose staging [n' (128)][m' (64)+pad], stride 65
    } sm;

    // map linear tile index -> (bi, bj) with bi <= bj
    int u = blockIdx.x;
    int bi = 0, rowlen = 32;
    while (u >= rowlen) { u -= rowlen; rowlen--; bi++; }
    const int bj = bi + u;

    const int b  = blockIdx.z;
    const int n0 = bi * 128;
    const int m0 = bj * 128;
    const float* base = g_xn + (size_t)b * CC * NN;
    const int tid = threadIdx.x;
    const int tx = tid & 15;        // m micro-tile
    const int ty = tid >> 4;        // n micro-tile

    float (*As)[128] = sm.ab[0];
    float (*Bs)[128] = sm.ab[1];

    float acc[8][8];
    #pragma unroll
    for (int i = 0; i < 8; i++)
        #pragma unroll
        for (int j = 0; j < 8; j++) acc[i][j] = 0.f;

    for (int c0 = 0; c0 < CC; c0 += 16) {
        for (int idx = tid; idx < 16 * 128; idx += 256) {
            int kk  = idx >> 7;
            int col = idx & 127;
            const float* src = base + (size_t)(c0 + kk) * NN;
            As[kk][col] = src[n0 + col];
            Bs[kk][col] = src[m0 + col];
        }
        __syncthreads();
        #pragma unroll
        for (int kk = 0; kk < 16; kk++) {
            float a[8], bv[8];
            #pragma unroll
            for (int i = 0; i < 8; i++) a[i]  = As[kk][ty * 8 + i];
            #pragma unroll
            for (int j = 0; j < 8; j++) bv[j] = Bs[kk][tx * 8 + j];
            #pragma unroll
            for (int i = 0; i < 8; i++)
                #pragma unroll
                for (int j = 0; j < 8; j++)
                    acc[i][j] += a[i] * bv[j];
        }
        __syncthreads();
    }

    const float* sqb = g_sq + (size_t)b * NN;

    // ---- normal tile (n rows, m cols) ----
    {
        float sqm[8];
        #pragma unroll
        for (int j = 0; j < 8; j++) sqm[j] = sqb[m0 + tx * 8 + j];
        #pragma unroll
        for (int i = 0; i < 8; i++) {
            int n = n0 + ty * 8 + i;
            float sqn = sqb[n];
            float* drow = g_dist + ((size_t)b * NN + n) * NN + m0 + tx * 8;
            #pragma unroll
            for (int j = 0; j < 8; j++)
                drow[j] = (sqn + (-2.0f * acc[i][j])) + sqm[j];
        }
    }

    // ---- mirrored tile (m rows, n cols), off-diagonal only ----
    if (bi != bj) {
        #pragma unroll 1
        for (int c = 0; c < 2; c++) {            // m'-chunks of 64
            __syncthreads();                     // previous users of sm done
            if ((tx >> 3) == c) {                // this half owns m' in chunk
                #pragma unroll
                for (int i = 0; i < 8; i++)
                    #pragma unroll
                    for (int j = 0; j < 8; j++)
                        sm.ts[(size_t)(ty * 8 + i) * 65 + ((tx & 7) * 8 + j)] = acc[i][j];
            }
            __syncthreads();
            // coalesced write of 64 rows x 128 cols
            const int lane = tid & 31;
            const int rbase = tid >> 5;          // 0..7
            #pragma unroll 1
            for (int rr = 0; rr < 8; rr++) {
                int r = rr * 8 + rbase;          // 0..63
                int m = m0 + c * 64 + r;
                float sqm_v = sqb[m];
                float* drow = g_dist + ((size_t)b * NN + m) * NN + n0;
                #pragma unroll
                for (int w = 0; w < 4; w++) {
                    int col = lane + 32 * w;
                    float t = sm.ts[(size_t)col * 65 + r];
                    drow[col] = (sqm_v + (-2.0f * t)) + sqb[n0 + col];
                }
            }
        }
    }
}

// ---------------------------------------------------------------------------
// Kernel 3: warp-per-row top-10 ascending (dist, idx); drop rank 0 (self).
// ---------------------------------------------------------------------------
__device__ __forceinline__ unsigned ford(float f) {
    unsigned u = __float_as_uint(f);
    return (u & 0x80000000u) ? ~u : (u | 0x80000000u);
}

__global__ void select_topk_kernel(float* __restrict__ out) {
    const int warp = (blockIdx.x * blockDim.x + threadIdx.x) >> 5;
    const int lane = threadIdx.x & 31;
    if (warp >= BB * NN) return;
    const int row = warp;
    const int b = row >> 12;
    const int n = row & (NN - 1);
    const float* drow = g_dist + (size_t)row * NN;

    float v[10]; int id[10];
    #pragma unroll
    for (int k = 0; k < 10; k++) { v[k] = 3.4e38f; id[k] = 0x7FFFFFFF; }

    for (int m = lane; m < NN; m += 32) {
        float val = drow[m];
        if ((val < v[9]) || (val == v[9] && m < id[9])) {
            v[9] = val; id[9] = m;
            #pragma unroll
            for (int k = 9; k > 0; k--) {
                bool sw = (v[k] < v[k-1]) || (v[k] == v[k-1] && id[k] < id[k-1]);
                if (sw) {
                    float tv = v[k]; v[k] = v[k-1]; v[k-1] = tv;
                    int ti = id[k]; id[k] = id[k-1]; id[k-1] = ti;
                }
            }
        }
    }

    const size_t L = (size_t)BB * NN * KK;
    const size_t outbase = (size_t)row * KK;
    int pos = 0;
    for (int k = 0; k < 10; k++) {
        unsigned long long myk = (pos < 10)
            ? (((unsigned long long)ford(v[pos]) << 32) | (unsigned)id[pos])
            : 0xFFFFFFFFFFFFFFFFULL;
        unsigned long long mn = myk;
        #pragma unroll
        for (int off = 16; off > 0; off >>= 1) {
            unsigned long long o = __shfl_xor_sync(0xFFFFFFFFu, mn, off);
            mn = (o < mn) ? o : mn;
        }
        if (myk == mn) pos++;
        if (k > 0 && lane == 0)
            out[outbase + (k - 1)] = (float)((int)(mn & 0xFFFFFFFFu) + b * NN);
    }
    if (lane < KK) out[L + outbase + lane] = (float)(n + b * NN);
}

// ---------------------------------------------------------------------------
extern "C" void kernel_launch(void* const* d_in, const int* in_sizes, int n_in,
                              void* d_out, int out_size) {
    const float* x = (const float*)d_in[0];
    float* out = (float*)d_out;

    { dim3 grid(NN / 256, BB); normalize_kernel<<<grid, 256>>>(x); }
    { dim3 grid(528, 1, BB); dist_gemm_sym_kernel<<<grid, 256>>>(); }
    { int rows = BB * NN; select_topk_kernel<<<(rows * 32 + 255) / 256, 256>>>(out); }
}

// round 12
// speedup vs baseline: 1.5021x; 1.0341x over previous
#include <cuda_runtime.h>
#include <cstdint>

#define BB 4
#define CC 192
#define NN 4096
#define KK 9
#define TK 16

__device__ __align__(256) float g_xn[(size_t)BB * CC * NN];   // normalized pts [b][c][n]
__device__ __align__(256) float g_sq[(size_t)BB * NN];        // per-point sum of squares
__device__ __align__(256) float g_dist[(size_t)BB * NN * NN]; // distance matrix

__device__ __forceinline__ void cp_async16(void* smem_dst, const void* gmem_src) {
    unsigned saddr = (unsigned)__cvta_generic_to_shared(smem_dst);
    asm volatile("cp.async.ca.shared.global [%0], [%1], 16;\n" :: "r"(saddr), "l"(gmem_src));
}
__device__ __forceinline__ void cp_commit() {
    asm volatile("cp.async.commit_group;\n");
}
template <int N>
__device__ __forceinline__ void cp_wait() {
    asm volatile("cp.async.wait_group %0;\n" :: "n"(N));
}

// ---------------------------------------------------------------------------
// Kernel 1: L2-normalize over channel dim. x layout [B][C][N], N = H*W.
// ---------------------------------------------------------------------------
__global__ void normalize_kernel(const float* __restrict__ x) {
    int b = blockIdx.y;
    int n = blockIdx.x * blockDim.x + threadIdx.x;
    if (n >= NN) return;
    const float* xb = x + (size_t)b * CC * NN + n;
    float s = 0.f;
    #pragma unroll 16
    for (int c = 0; c < CC; c++) { float v = xb[(size_t)c * NN]; s += v * v; }
    float denom = fmaxf(sqrtf(s), 1e-12f);
    float* xnb = g_xn + (size_t)b * CC * NN + n;
    float sq = 0.f;
    #pragma unroll 16
    for (int c = 0; c < CC; c++) {
        float p = xb[(size_t)c * NN] / denom;
        xnb[(size_t)c * NN] = p;
        sq += p * p;
    }
    g_sq[(size_t)b * NN + n] = sq;
}

// ---------------------------------------------------------------------------
// Kernel 2: symmetric distance GEMM, cp.async double-buffered loads.
// Inner compute loop identical to rounds 8/11 (scalar fragment reads, same
// accumulation order). Upper-triangular tiles only; mirrored tile written
// via chunked smem transpose (4 chunks of 32 m-cols; ts = 128x33).
// ---------------------------------------------------------------------------
__global__ __launch_bounds__(256) void dist_gemm_sym_kernel() {
    __shared__ union {
        float ab[2][2][TK][128];   // [buf][A=0/B=1][k][col]  -> 32 KB
        float ts[128 * 33];        // transpose staging        -> 16.9 KB
    } sm;

    // map linear tile index -> (bi, bj) with bi <= bj
    int u = blockIdx.x;
    int bi = 0, rowlen = 32;
    while (u >= rowlen) { u -= rowlen; rowlen--; bi++; }
    const int bj = bi + u;

    const int b  = blockIdx.z;
    const int n0 = bi * 128;
    const int m0 = bj * 128;
    const float* base = g_xn + (size_t)b * CC * NN;
    const int tid = threadIdx.x;
    const int tx = tid & 15;        // m micro-tile
    const int ty = tid >> 4;        // n micro-tile

    // loader: each thread fills rows lr and lr+8, one float4 column slot
    const int lr = tid >> 5;        // 0..7
    const int lc = (tid & 31) * 4;  // 0..124

    const int NT = CC / TK;         // 12

    // preload tile 0 into buffer 0
    {
        const float* s0 = base + (size_t)lr * NN;
        const float* s1 = base + (size_t)(lr + 8) * NN;
        cp_async16(&sm.ab[0][0][lr][lc],     s0 + n0 + lc);
        cp_async16(&sm.ab[0][0][lr + 8][lc], s1 + n0 + lc);
        cp_async16(&sm.ab[0][1][lr][lc],     s0 + m0 + lc);
        cp_async16(&sm.ab[0][1][lr + 8][lc], s1 + m0 + lc);
        cp_commit();
    }

    float acc[8][8];
    #pragma unroll
    for (int i = 0; i < 8; i++)
        #pragma unroll
        for (int j = 0; j < 8; j++) acc[i][j] = 0.f;

    #pragma unroll 1
    for (int t = 0; t < NT; t++) {
        const int cur = t & 1;

        if (t + 1 < NT) {
            const int c1 = (t + 1) * TK;
            const float* s0 = base + (size_t)(c1 + lr) * NN;
            const float* s1 = base + (size_t)(c1 + lr + 8) * NN;
            cp_async16(&sm.ab[cur ^ 1][0][lr][lc],     s0 + n0 + lc);
            cp_async16(&sm.ab[cur ^ 1][0][lr + 8][lc], s1 + n0 + lc);
            cp_async16(&sm.ab[cur ^ 1][1][lr][lc],     s0 + m0 + lc);
            cp_async16(&sm.ab[cur ^ 1][1][lr + 8][lc], s1 + m0 + lc);
            cp_commit();
            cp_wait<1>();   // current tile complete; prefetch still in flight
        } else {
            cp_wait<0>();
        }
        __syncthreads();

        const float (*As)[128] = sm.ab[cur][0];
        const float (*Bs)[128] = sm.ab[cur][1];
        #pragma unroll
        for (int kk = 0; kk < TK; kk++) {
            float a[8], bv[8];
            #pragma unroll
            for (int i = 0; i < 8; i++) a[i]  = As[kk][ty * 8 + i];
            #pragma unroll
            for (int j = 0; j < 8; j++) bv[j] = Bs[kk][tx * 8 + j];
            #pragma unroll
            for (int i = 0; i < 8; i++)
                #pragma unroll
                for (int j = 0; j < 8; j++)
                    acc[i][j] += a[i] * bv[j];
        }
        __syncthreads();   // done reading cur before next prefetch overwrites
    }

    const float* sqb = g_sq + (size_t)b * NN;

    // ---- normal tile (n rows, m cols) ----
    {
        float sqm[8];
        #pragma unroll
        for (int j = 0; j < 8; j++) sqm[j] = sqb[m0 + tx * 8 + j];
        #pragma unroll
        for (int i = 0; i < 8; i++) {
            int n = n0 + ty * 8 + i;
            float sqn = sqb[n];
            float* drow = g_dist + ((size_t)b * NN + n) * NN + m0 + tx * 8;
            #pragma unroll
            for (int j = 0; j < 8; j++)
                drow[j] = (sqn + (-2.0f * acc[i][j])) + sqm[j];
        }
    }

    // ---- mirrored tile (m rows, n cols), off-diagonal only ----
    if (bi != bj) {
        #pragma unroll 1
        for (int c = 0; c < 4; c++) {            // m'-chunks of 32
            __syncthreads();                     // prior smem users done
            if ((tx >> 2) == c) {                // owners of this m'-chunk
                #pragma unroll
                for (int i = 0; i < 8; i++)
                    #pragma unroll
                    for (int j = 0; j < 8; j++)
                        sm.ts[(size_t)(ty * 8 + i) * 33 + ((tx & 3) * 8 + j)] = acc[i][j];
            }
            __syncthreads();
            // coalesced write of 32 rows x 128 cols
            const int lane = tid & 31;
            const int rbase = tid >> 5;          // 0..7
            #pragma unroll
            for (int rr = 0; rr < 4; rr++) {
                int r = rr * 8 + rbase;          // 0..31
                int m = m0 + c * 32 + r;
                float sqm_v = sqb[m];
                float* drow = g_dist + ((size_t)b * NN + m) * NN + n0;
                #pragma unroll
                for (int w = 0; w < 4; w++) {
                    int col = lane + 32 * w;
                    float tval = sm.ts[(size_t)col * 33 + r];
                    drow[col] = (sqm_v + (-2.0f * tval)) + sqb[n0 + col];
                }
            }
        }
    }
}

// ---------------------------------------------------------------------------
// Kernel 3: warp-per-row top-10 ascending (dist, idx); drop rank 0 (self).
// ---------------------------------------------------------------------------
__device__ __forceinline__ unsigned ford(float f) {
    unsigned u = __float_as_uint(f);
    return (u & 0x80000000u) ? ~u : (u | 0x80000000u);
}

__global__ void select_topk_kernel(float* __restrict__ out) {
    const int warp = (blockIdx.x * blockDim.x + threadIdx.x) >> 5;
    const int lane = threadIdx.x & 31;
    if (warp >= BB * NN) return;
    const int row = warp;
    const int b = row >> 12;
    const int n = row & (NN - 1);
    const float* drow = g_dist + (size_t)row * NN;

    float v[10]; int id[10];
    #pragma unroll
    for (int k = 0; k < 10; k++) { v[k] = 3.4e38f; id[k] = 0x7FFFFFFF; }

    for (int m = lane; m < NN; m += 32) {
        float val = drow[m];
        if ((val < v[9]) || (val == v[9] && m < id[9])) {
            v[9] = val; id[9] = m;
            #pragma unroll
            for (int k = 9; k > 0; k--) {
                bool sw = (v[k] < v[k-1]) || (v[k] == v[k-1] && id[k] < id[k-1]);
                if (sw) {
                    float tv = v[k]; v[k] = v[k-1]; v[k-1] = tv;
                    int ti = id[k]; id[k] = id[k-1]; id[k-1] = ti;
                }
            }
        }
    }

    const size_t L = (size_t)BB * NN * KK;
    const size_t outbase = (size_t)row * KK;
    int pos = 0;
    for (int k = 0; k < 10; k++) {
        unsigned long long myk = (pos < 10)
            ? (((unsigned long long)ford(v[pos]) << 32) | (unsigned)id[pos])
            : 0xFFFFFFFFFFFFFFFFULL;
        unsigned long long mn = myk;
        #pragma unroll
        for (int off = 16; off > 0; off >>= 1) {
            unsigned long long o = __shfl_xor_sync(0xFFFFFFFFu, mn, off);
            mn = (o < mn) ? o : mn;
        }
        if (myk == mn) pos++;
        if (k > 0 && lane == 0)
            out[outbase + (k - 1)] = (float)((int)(mn & 0xFFFFFFFFu) + b * NN);
    }
    if (lane < KK) out[L + outbase + lane] = (float)(n + b * NN);
}

// ---------------------------------------------------------------------------
extern "C" void kernel_launch(void* const* d_in, const int* in_sizes, int n_in,
                              void* d_out, int out_size) {
    const float* x = (const float*)d_in[0];
    float* out = (float*)d_out;

    { dim3 grid(NN / 256, BB); normalize_kernel<<<grid, 256>>>(x); }
    { dim3 grid(528, 1, BB); dist_gemm_sym_kernel<<<grid, 256>>>(); }
    { int rows = BB * NN; select_topk_kernel<<<(rows * 32 + 255) / 256, 256>>>(out); }
}